// round 11
// baseline (speedup 1.0000x reference)
#include <cuda_runtime.h>
#include <cuda_bf16.h>
#include <cuda_fp16.h>
#include <math.h>

#define NBASE 40000
#define NJOINT 480000
#define NFOOT 160000
#define HDIM 128
#define NEG_SLOPE 0.2f
#define RSTR 481280      // padded per-role segment stride (= 470*1024)
#define NBLK 470         // 1024-elem scan blocks per segment

// ---------------- scratch (device globals; ~1.0 GB, linker-safe) ----------------
__device__ __half g_bufA[(size_t)680000 * 128];   // x / agg ping-pong (fp16 storage)
__device__ __half g_bufB[(size_t)680000 * 128];
__device__ __half g_pool[(size_t)1680000 * 128];  // compact xl/xr rows (fp16)
__device__ __nv_bfloat16 g_Wthi[40 * 16384];
__device__ __nv_bfloat16 g_Wtlo[40 * 16384];
__device__ int g_rank[10 * RSTR];
__device__ int g_list[10 * RSTR];
__device__ int g_scan[10 * RSTR];
__device__ int g_deg[5 * RSTR];
__device__ int g_off5[5 * RSTR];
__device__ int g_cur5[5 * RSTR];
__device__ int g_csr[960000];
__device__ int g_cdst[960000];      // compact dst per CSR slot
__device__ unsigned g_menc[5 * RSTR];  // per-type segment-max (encoded), compact-dst indexed
__device__ float g_sbuf[960000];    // per-edge logits
__device__ int g_cnt[16];
__device__ int g_part[10 * 512];

// ---------------- helpers ----------------
static __device__ __forceinline__ void bf16split(float v, __nv_bfloat16& h, __nv_bfloat16& l) {
    h = __float2bfloat16(v);
    l = __float2bfloat16(v - __bfloat162float(h));
}
static __device__ __forceinline__ unsigned fenc(float f) {
    unsigned u = __float_as_uint(f);
    return (u & 0x80000000u) ? ~u : (u | 0x80000000u);
}
static __device__ __forceinline__ float fdec(unsigned u) {
    return (u & 0x80000000u) ? __uint_as_float(u ^ 0x80000000u) : __uint_as_float(~u);
}

__global__ void wprep_k(const float* __restrict__ Wl, const float* __restrict__ Wr,
                        __nv_bfloat16* __restrict__ hi, __nv_bfloat16* __restrict__ lo) {
    int idx = blockIdx.x * 256 + threadIdx.x;
    if (idx >= 40 * 16384) return;
    int m = idx >> 14, e = idx & 16383;
    int n = e >> 7, k = e & 127;
    const float* src = (m < 20) ? (Wl + (size_t)m * 16384) : (Wr + (size_t)(m - 20) * 16384);
    float v = src[k * 128 + n];
    __nv_bfloat16 h, l;
    bf16split(v, h, l);
    hi[idx] = h; lo[idx] = l;
}

// vectorized encoder
__global__ void encode_k(const float* __restrict__ x, const float* __restrict__ W,
                         const float* __restrict__ b, __half* __restrict__ y, int N, int K) {
    int idx = blockIdx.x * 256 + threadIdx.x;
    if (idx >= N * 32) return;
    int n = idx >> 5, q = idx & 31;
    float4 acc = ((const float4*)b)[q];
    for (int k = 0; k < K; k++) {
        float xv = __ldg(x + (size_t)n * K + k);
        float4 w = ((const float4*)W)[k * 32 + q];
        acc.x += xv * w.x; acc.y += xv * w.y; acc.z += xv * w.z; acc.w += xv * w.w;
    }
    __half2 h0 = __floats2half2_rn(fmaxf(acc.x, 0.f), fmaxf(acc.y, 0.f));
    __half2 h1 = __floats2half2_rn(fmaxf(acc.z, 0.f), fmaxf(acc.w, 0.f));
    uint2 p;
    p.x = *(unsigned*)&h0;
    p.y = *(unsigned*)&h1;
    *(uint2*)(y + (size_t)n * 128 + q * 4) = p;
}

// ---------------- batched prep ----------------
struct EL {
    const int* src[5];
    const int* dst[5];
    int cumE[6];
};
struct NArr { int N[10]; };

__global__ void mark_all_k(EL el, int total) {
    int gi = blockIdx.x * 256 + threadIdx.x;
    if (gi >= 2 * total) return;
    int side = gi >= total;
    int j = gi - side * total;
    int t = 0;
    while (j >= el.cumE[t + 1]) t++;
    int e = j - el.cumE[t];
    int node = side ? el.dst[t][e] : el.src[t][e];
    g_rank[(2 * t + side) * RSTR + node] = 1;
}

__global__ void bscan1_k(const int* __restrict__ v, int* __restrict__ out,
                         int* __restrict__ part) {
    __shared__ int sh[1024];
    int r = blockIdx.x / NBLK, j = blockIdx.x % NBLK;
    int i = r * RSTR + j * 1024 + threadIdx.x;
    int val = v[i];
    sh[threadIdx.x] = val;
    __syncthreads();
#pragma unroll
    for (int o = 1; o < 1024; o <<= 1) {
        int t = (threadIdx.x >= o) ? sh[threadIdx.x - o] : 0;
        __syncthreads();
        sh[threadIdx.x] += t;
        __syncthreads();
    }
    int incl = sh[threadIdx.x];
    out[i] = incl - val;
    if (threadIdx.x == 1023) part[r * 512 + j] = incl;
}
__global__ void bscan2_k(int* part) {
    __shared__ int sh[512];
    int r = blockIdx.x;
    int v = (threadIdx.x < NBLK) ? part[r * 512 + threadIdx.x] : 0;
    sh[threadIdx.x] = v;
    __syncthreads();
#pragma unroll
    for (int o = 1; o < 512; o <<= 1) {
        int t = (threadIdx.x >= o) ? sh[threadIdx.x - o] : 0;
        __syncthreads();
        sh[threadIdx.x] += t;
        __syncthreads();
    }
    if (threadIdx.x < NBLK) part[r * 512 + threadIdx.x] = sh[threadIdx.x] - v;
}
__global__ void bscan3_k(int* __restrict__ out, const int* __restrict__ part) {
    int r = blockIdx.x / NBLK, j = blockIdx.x % NBLK;
    int i = r * RSTR + j * 1024 + threadIdx.x;
    out[i] += part[r * 512 + j];
}

__global__ void bcompact_k(NArr na) {
    int i = blockIdx.x * 256 + threadIdx.x;
    if (i >= 10 * RSTR) return;
    int r = i / RSTR, li = i % RSTR;
    if (li >= na.N[r]) return;
    if (g_rank[i]) {
        int pos = g_scan[i];
        g_list[r * RSTR + pos] = li;
        g_rank[i] = pos;
    } else {
        g_rank[i] = -1;
    }
}
__global__ void getcnt_k(NArr na) {
    int r = threadIdx.x;
    if (r < 10) g_cnt[r] = g_scan[r * RSTR + na.N[r]];
}

__global__ void bhist_k(EL el, int total) {
    int j = blockIdx.x * 256 + threadIdx.x;
    if (j >= total) return;
    int t = 0;
    while (j >= el.cumE[t + 1]) t++;
    int e = j - el.cumE[t];
    atomicAdd(&g_deg[t * RSTR + el.dst[t][e]], 1);
}
__global__ void bfill_k(EL el, int total) {
    int j = blockIdx.x * 256 + threadIdx.x;
    if (j >= total) return;
    int t = 0;
    while (j >= el.cumE[t + 1]) t++;
    int e = j - el.cumE[t];
    int d = el.dst[t][e];
    int p = atomicAdd(&g_cur5[t * RSTR + d], 1);
    int pos = el.cumE[t] + p;
    g_csr[pos] = g_rank[(2 * t) * RSTR + el.src[t][e]];
    g_cdst[pos] = g_rank[(2 * t + 1) * RSTR + d];
}

__global__ void fill_menc_k() {
    int i = blockIdx.x * 256 + threadIdx.x;
    if (i < 5 * RSTR) g_menc[i] = 0x007FFFFFu;   // fenc(-inf)
}

// ---------------- batched gather-GEMM (M-tile 64, dual-CTA, fp16 I/O) ----------------
#define SAE 8704    // 64*136 bf16 elems (A matrix)
#define SBE 17408   // 128*136 bf16 elems (B matrix)

#define LDSM4(R, addr) asm volatile( \
    "ldmatrix.sync.aligned.m8n8.x4.shared.b16 {%0,%1,%2,%3}, [%4];" \
    : "=r"((R)[0]), "=r"((R)[1]), "=r"((R)[2]), "=r"((R)[3]) : "r"(addr))

#define MMA16816(C, A, b0, b1) asm volatile( \
    "mma.sync.aligned.m16n8k16.row.col.f32.bf16.bf16.f32 " \
    "{%0,%1,%2,%3},{%4,%5,%6,%7},{%8,%9},{%0,%1,%2,%3};" \
    : "+f"((C)[0]), "+f"((C)[1]), "+f"((C)[2]), "+f"((C)[3]) \
    : "r"((A)[0]), "r"((A)[1]), "r"((A)[2]), "r"((A)[3]), "r"(b0), "r"(b1))

static __device__ __forceinline__ void cpasync16(unsigned dst, const void* src, int sz) {
    asm volatile("cp.async.cg.shared.global [%0], [%1], 16, %2;" :: "r"(dst), "l"(src), "r"(sz));
}

struct GR {
    const __half* A;
    const int* rowlist;
    const int* cntPtr;
    const __nv_bfloat16* Bhi;
    const __nv_bfloat16* Blo;
    const float* bias;
    __half* out;
};
struct GB { GR r[10]; int cum[11]; int n; };

__global__ void __launch_bounds__(256, 2) gemm_batch_k(GB gb) {
    int b = blockIdx.x;
    int k = 0;
    while (k < gb.n - 1 && b >= gb.cum[k + 1]) k++;
    GR R = gb.r[k];
    const int cnt = *R.cntPtr;
    const int row0 = (b - gb.cum[k]) * 64;
    if (row0 >= cnt) return;

    extern __shared__ __nv_bfloat16 smem[];
    const int tid = threadIdx.x;
    unsigned sAhi = (unsigned)__cvta_generic_to_shared(smem);
    unsigned sB = sAhi + 2 * SAE * 2;

#pragma unroll
    for (int i = 0; i < 8; i++) {
        int chunk = tid + i * 256;
        int row = chunk >> 4;
        int col = (chunk & 15) * 8;
        size_t off = (size_t)row * 128 + col;
        unsigned d = sB + (unsigned)(row * 136 + col) * 2;
        cpasync16(d, R.Bhi + off, 16);
        cpasync16(d + SBE * 2, R.Blo + off, 16);
    }
    asm volatile("cp.async.commit_group;");

#pragma unroll
    for (int i = 0; i < 4; i++) {
        int chunk = tid + i * 256;
        int row = chunk >> 4;
        int c8 = (chunk & 15) * 8;
        int ok = (row0 + row) < cnt;
        int node = ok ? R.rowlist[row0 + row] : 0;
        uint4 raw = ok ? *(const uint4*)(R.A + (size_t)node * 128 + c8)
                       : make_uint4(0u, 0u, 0u, 0u);
        const __half2* hp = (const __half2*)&raw;
        int base = row * 136 + c8;
#pragma unroll
        for (int q = 0; q < 4; q++) {
            float2 f = __half22float2(hp[q]);
            f.x = fmaxf(f.x, 0.f);
            f.y = fmaxf(f.y, 0.f);
            __nv_bfloat16 h0, l0, h1, l1;
            bf16split(f.x, h0, l0);
            bf16split(f.y, h1, l1);
            *(__nv_bfloat162*)(smem + base + 2 * q)       = __nv_bfloat162(h0, h1);
            *(__nv_bfloat162*)(smem + SAE + base + 2 * q) = __nv_bfloat162(l0, l1);
        }
    }
    asm volatile("cp.async.wait_group 0;");
    __syncthreads();

    int warp = tid >> 5, lane = tid & 31;
    int m0 = (warp >> 2) * 32;
    int n0 = (warp & 3) * 32;
    int frow = lane & 15;
    int fcolo = (lane >> 4) * 8;

    float acc[2][4][4];
#pragma unroll
    for (int a = 0; a < 2; a++)
#pragma unroll
        for (int c = 0; c < 4; c++)
#pragma unroll
            for (int r = 0; r < 4; r++) acc[a][c][r] = 0.f;

    for (int ks = 0; ks < 8; ks++) {
        int acol = ks * 16 + fcolo;
        unsigned ah[2][4], al[2][4];
#pragma unroll
        for (int mt = 0; mt < 2; mt++) {
            unsigned ad = sAhi + (unsigned)((m0 + mt * 16 + frow) * 136 + acol) * 2;
            LDSM4(ah[mt], ad);
            LDSM4(al[mt], ad + SAE * 2);
        }
        unsigned bh[2][4], blx[2][4];
#pragma unroll
        for (int p = 0; p < 2; p++) {
            unsigned bd = sB + (unsigned)((n0 + p * 16 + frow) * 136 + acol) * 2;
            LDSM4(bh[p], bd);
            LDSM4(blx[p], bd + SBE * 2);
        }
#pragma unroll
        for (int mt = 0; mt < 2; mt++)
#pragma unroll
            for (int nt = 0; nt < 4; nt++) {
                int p = nt >> 1, o = nt & 1;
                MMA16816(acc[mt][nt], ah[mt], bh[p][o], bh[p][2 + o]);
                MMA16816(acc[mt][nt], ah[mt], blx[p][o], blx[p][2 + o]);
                MMA16816(acc[mt][nt], al[mt], bh[p][o], bh[p][2 + o]);
            }
    }

    int crow = lane >> 2, ccol = (lane & 3) * 2;
#pragma unroll
    for (int nt = 0; nt < 4; nt++) {
        int col = n0 + nt * 8 + ccol;
        float b0v = R.bias[col], b1v = R.bias[col + 1];
#pragma unroll
        for (int mt = 0; mt < 2; mt++) {
            int r = row0 + m0 + mt * 16 + crow;
            if (r < cnt)
                *(__half2*)(R.out + (size_t)r * 128 + col) =
                    __floats2half2_rn(acc[mt][nt][0] + b0v, acc[mt][nt][1] + b1v);
            if (r + 8 < cnt)
                *(__half2*)(R.out + (size_t)(r + 8) * 128 + col) =
                    __floats2half2_rn(acc[mt][nt][2] + b0v, acc[mt][nt][3] + b1v);
        }
    }
}

// ---------------- edge pass 1: batched edge-parallel logits + segment max ----------------
static __device__ __forceinline__ float4 ldh4(const __half* p) {
    uint2 raw = *(const uint2*)p;
    const __half2* hp = (const __half2*)&raw;
    float2 a = __half22float2(hp[0]);
    float2 b = __half22float2(hp[1]);
    return make_float4(a.x, a.y, b.x, b.y);
}

static __device__ __forceinline__ float edge_logit(float4 xv, float4 xr4, float4 at) {
    float t0 = xv.x + xr4.x, t1 = xv.y + xr4.y, t2 = xv.z + xr4.z, t3 = xv.w + xr4.w;
    t0 = t0 > 0.f ? t0 : NEG_SLOPE * t0;
    t1 = t1 > 0.f ? t1 : NEG_SLOPE * t1;
    t2 = t2 > 0.f ? t2 : NEG_SLOPE * t2;
    t3 = t3 > 0.f ? t3 : NEG_SLOPE * t3;
    return t0 * at.x + t1 * at.y + t2 * at.z + t3 * at.w;
}

struct P1T {
    const __half* xl;
    const __half* xr;
    const int* csr;    // compact src per slot
    const int* cdst;   // compact dst per slot
    const float* att;
    float* sb;
    unsigned* menc;
};
struct P1Args { P1T t[5]; int cum[6]; int n; };

__global__ void p1_k(P1Args a) {
    int blk = blockIdx.x;
    int k = 0;
    while (k < a.n - 1 && blk >= a.cum[k + 1]) k++;
    const P1T& t = a.t[k];
    int j = (blk - a.cum[k]) * 8 + (threadIdx.x >> 5);
    int lane = threadIdx.x & 31;
    int si = t.csr[j], di = t.cdst[j];
    float4 xl4 = ldh4(t.xl + (size_t)si * 128 + lane * 4);
    float4 xr4 = ldh4(t.xr + (size_t)di * 128 + lane * 4);
    float4 at = ((const float4*)t.att)[lane];
    float p = edge_logit(xl4, xr4, at);
#pragma unroll
    for (int o = 16; o; o >>= 1) p += __shfl_xor_sync(0xffffffffu, p, o);
    if (lane == 0) {
        t.sb[j] = p;
        atomicMax(t.menc + di, fenc(p));
    }
}

// ---------------- edge pass 2: dst-parallel, shuffle-free softmax ----------------
struct EdgeT {
    const __half* xl;
    const int* csr;
    const int* off;
    const int* rank;
    const float* bias;
    const unsigned* menc;
    const float* sb;
};

static __device__ __forceinline__ void proc_one(const EdgeT& t, int d, int lane, float4& r) {
    float4 bb = ((const float4*)t.bias)[lane];
    r.x += bb.x; r.y += bb.y; r.z += bb.z; r.w += bb.w;
    int s0 = t.off[d], s1 = t.off[d + 1];
    if (s1 <= s0) return;
    int cr = t.rank[d];
    float m = fdec(t.menc[cr]);
    float den = 0.f, a0 = 0.f, a1 = 0.f, a2 = 0.f, a3 = 0.f;
    int e = s0;
    for (; e + 1 < s1; e += 2) {
        int si0 = t.csr[e], si1 = t.csr[e + 1];
        float w0 = __expf(t.sb[e] - m);
        float w1 = __expf(t.sb[e + 1] - m);
        float4 x0 = ldh4(t.xl + (size_t)si0 * 128 + lane * 4);
        float4 x1 = ldh4(t.xl + (size_t)si1 * 128 + lane * 4);
        den += w0 + w1;
        a0 += w0 * x0.x + w1 * x1.x;
        a1 += w0 * x0.y + w1 * x1.y;
        a2 += w0 * x0.z + w1 * x1.z;
        a3 += w0 * x0.w + w1 * x1.w;
    }
    if (e < s1) {
        int si = t.csr[e];
        float w = __expf(t.sb[e] - m);
        float4 xv = ldh4(t.xl + (size_t)si * 128 + lane * 4);
        den += w;
        a0 += w * xv.x; a1 += w * xv.y; a2 += w * xv.z; a3 += w * xv.w;
    }
    float inv = 1.f / den;
    r.x += a0 * inv; r.y += a1 * inv; r.z += a2 * inv; r.w += a3 * inv;
}

static __device__ __forceinline__ void store_agg(__half* agg, int d, int lane, float4 r) {
    __half2 p0 = __floats2half2_rn(r.x, r.y);
    __half2 p1 = __floats2half2_rn(r.z, r.w);
    uint2 packed;
    packed.x = *(unsigned*)&p0;
    packed.y = *(unsigned*)&p1;
    *(uint2*)(agg + (size_t)d * 128 + lane * 4) = packed;
}

struct LayerED {
    EdgeT tJ0, tJ1, tJ2;
    EdgeT tB;
    EdgeT tF;
    __half *aggJ, *aggB, *aggF;
    int bB0, bF0;
    const float* Wdec;
    const float* bdec;
    float* dec_out;
    int doDecode;
};

__global__ void edge_layer_k(LayerED L) {
    int blk = blockIdx.x;
    int w = threadIdx.x >> 5;
    int lane = threadIdx.x & 31;
    float4 r = make_float4(0.f, 0.f, 0.f, 0.f);
    if (blk < L.bB0) {
        int d = blk * 8 + w;
        proc_one(L.tJ0, d, lane, r);
        proc_one(L.tJ1, d, lane, r);
        proc_one(L.tJ2, d, lane, r);
        store_agg(L.aggJ, d, lane, r);
    } else if (blk < L.bF0) {
        int d = (blk - L.bB0) * 8 + w;
        proc_one(L.tB, d, lane, r);
        store_agg(L.aggB, d, lane, r);
    } else {
        int d = (blk - L.bF0) * 8 + w;
        proc_one(L.tF, d, lane, r);
        if (!L.doDecode) {
            store_agg(L.aggF, d, lane, r);
        } else {
            r.x = fmaxf(r.x, 0.f); r.y = fmaxf(r.y, 0.f);
            r.z = fmaxf(r.z, 0.f); r.w = fmaxf(r.w, 0.f);
            int h = lane * 4;
            const float* W = L.Wdec;
            float s0 = r.x * W[(h + 0) * 3 + 0] + r.y * W[(h + 1) * 3 + 0] + r.z * W[(h + 2) * 3 + 0] + r.w * W[(h + 3) * 3 + 0];
            float s1 = r.x * W[(h + 0) * 3 + 1] + r.y * W[(h + 1) * 3 + 1] + r.z * W[(h + 2) * 3 + 1] + r.w * W[(h + 3) * 3 + 1];
            float s2 = r.x * W[(h + 0) * 3 + 2] + r.y * W[(h + 1) * 3 + 2] + r.z * W[(h + 2) * 3 + 2] + r.w * W[(h + 3) * 3 + 2];
#pragma unroll
            for (int o = 16; o; o >>= 1) {
                s0 += __shfl_xor_sync(0xffffffffu, s0, o);
                s1 += __shfl_xor_sync(0xffffffffu, s1, o);
                s2 += __shfl_xor_sync(0xffffffffu, s2, o);
            }
            if (lane == 0) {
                L.dec_out[d * 3 + 0] = s0 + L.bdec[0];
                L.dec_out[d * 3 + 1] = s1 + L.bdec[1];
                L.dec_out[d * 3 + 2] = s2 + L.bdec[2];
            }
        }
    }
}

// ---------------- host orchestration ----------------
extern "C" void kernel_launch(void* const* d_in, const int* in_sizes, int n_in,
                              void* d_out, int out_size) {
    int I[27];
    if (in_sizes[1] == 768) {
        const int m[27] = {0, 3, 6, 1, 2, 4, 5, 7, 8,
                           19, 20, 21, 22, 23, 24, 25, 26,
                           9, 10, 11, 12, 13, 14, 15, 16, 17, 18};
        for (int i = 0; i < 27; i++) I[i] = m[i];
    } else {
        for (int i = 0; i < 27; i++) I[i] = i;
    }

    const float* x_in[3] = {(const float*)d_in[I[0]], (const float*)d_in[I[1]], (const float*)d_in[I[2]]};
    const float* Wenc[3] = {(const float*)d_in[I[3]], (const float*)d_in[I[5]], (const float*)d_in[I[7]]};
    const float* benc[3] = {(const float*)d_in[I[4]], (const float*)d_in[I[6]], (const float*)d_in[I[8]]};
    const float* Wl = (const float*)d_in[I[9]];
    const float* bl = (const float*)d_in[I[10]];
    const float* Wr = (const float*)d_in[I[11]];
    const float* br = (const float*)d_in[I[12]];
    const float* att = (const float*)d_in[I[13]];
    const float* cb = (const float*)d_in[I[14]];
    const float* Wdec = (const float*)d_in[I[15]];
    const float* bdec = (const float*)d_in[I[16]];
    const int *srcA[5], *dstA[5];
    int E[5];
    for (int t = 0; t < 5; t++) {
        srcA[t] = (const int*)d_in[I[17 + 2 * t]];
        dstA[t] = (const int*)d_in[I[18 + 2 * t]];
        E[t] = in_sizes[I[17 + 2 * t]];
    }

    __half *bufA, *bufB, *pool;
    __nv_bfloat16 *Wthi, *Wtlo;
    int *rankB, *listB, *scanB, *degB, *off5, *cur5, *csrB, *cdstB, *cnt, *part;
    unsigned* mencB;
    float* sbufB;
    cudaGetSymbolAddress((void**)&bufA, g_bufA);
    cudaGetSymbolAddress((void**)&bufB, g_bufB);
    cudaGetSymbolAddress((void**)&pool, g_pool);
    cudaGetSymbolAddress((void**)&Wthi, g_Wthi);
    cudaGetSymbolAddress((void**)&Wtlo, g_Wtlo);
    cudaGetSymbolAddress((void**)&rankB, g_rank);
    cudaGetSymbolAddress((void**)&listB, g_list);
    cudaGetSymbolAddress((void**)&scanB, g_scan);
    cudaGetSymbolAddress((void**)&degB, g_deg);
    cudaGetSymbolAddress((void**)&off5, g_off5);
    cudaGetSymbolAddress((void**)&cur5, g_cur5);
    cudaGetSymbolAddress((void**)&csrB, g_csr);
    cudaGetSymbolAddress((void**)&cdstB, g_cdst);
    cudaGetSymbolAddress((void**)&mencB, g_menc);
    cudaGetSymbolAddress((void**)&sbufB, g_sbuf);
    cudaGetSymbolAddress((void**)&cnt, g_cnt);
    cudaGetSymbolAddress((void**)&part, g_part);

    const int Nn[3] = {NBASE, NJOINT, NFOOT};
    const int Kin[3] = {6, 2, 4};
    const size_t XOFF[3] = {0, (size_t)NBASE * 128, (size_t)(NBASE + NJOINT) * 128};
    const int sT[5] = {0, 1, 1, 1, 2};
    const int dT[5] = {1, 0, 1, 2, 1};
    const size_t POOL[10] = {0, 40000, 200000, 360000, 400000, 720000, 1040000, 1200000, 1360000, 1520000};
    const int GRIDR[10] = {625, 2500, 2500, 625, 5000, 5000, 2500, 2500, 2500, 2500};

    const int SMEM = (2 * SAE + 2 * SBE) * 2;
    cudaFuncSetAttribute(gemm_batch_k, cudaFuncAttributeMaxDynamicSharedMemorySize, SMEM);

    // ---- once-per-call prep ----
    wprep_k<<<(40 * 16384 + 255) / 256, 256>>>(Wl, Wr, Wthi, Wtlo);
    for (int t = 0; t < 3; t++)
        encode_k<<<(Nn[t] * 32 + 255) / 256, 256>>>(
            x_in[t], Wenc[t], benc[t], bufA + XOFF[t], Nn[t], Kin[t]);

    EL el;
    el.cumE[0] = 0;
    for (int t = 0; t < 5; t++) {
        el.src[t] = srcA[t];
        el.dst[t] = dstA[t];
        el.cumE[t + 1] = el.cumE[t] + E[t];
    }
    int Etot = el.cumE[5];
    NArr na;
    for (int ei = 0; ei < 5; ei++) {
        na.N[2 * ei] = Nn[sT[ei]];
        na.N[2 * ei + 1] = Nn[dT[ei]];
    }

    // role compaction (batched)
    cudaMemsetAsync(rankB, 0, (size_t)10 * RSTR * 4);
    mark_all_k<<<(2 * Etot + 255) / 256, 256>>>(el, Etot);
    bscan1_k<<<10 * NBLK, 1024>>>(rankB, scanB, part);
    bscan2_k<<<10, 512>>>(part);
    bscan3_k<<<10 * NBLK, 1024>>>(scanB, part);
    bcompact_k<<<(10 * RSTR + 255) / 256, 256>>>(na);
    getcnt_k<<<1, 16>>>(na);

    // CSR build (batched)
    cudaMemsetAsync(degB, 0, (size_t)5 * RSTR * 4);
    bhist_k<<<(Etot + 255) / 256, 256>>>(el, Etot);
    bscan1_k<<<5 * NBLK, 1024>>>(degB, off5, part);
    bscan2_k<<<5, 512>>>(part);
    bscan3_k<<<5 * NBLK, 1024>>>(off5, part);
    cudaMemcpyAsync(cur5, off5, (size_t)5 * RSTR * 4, cudaMemcpyDeviceToDevice);
    bfill_k<<<(Etot + 255) / 256, 256>>>(el, Etot);

    __half* x = bufA;
    __half* agg = bufB;

    auto makeRole = [&](int ei, int side, int l) {
        int role = 2 * ei + side;
        int po = l * 5 + ei;
        int wIdx = side ? (20 + po) : po;
        GR R;
        R.A = x + XOFF[side ? dT[ei] : sT[ei]];
        R.rowlist = listB + (size_t)role * RSTR;
        R.cntPtr = cnt + role;
        R.Bhi = Wthi + (size_t)wIdx * 16384;
        R.Blo = Wtlo + (size_t)wIdx * 16384;
        R.bias = side ? (br + (size_t)po * 128) : (bl + (size_t)po * 128);
        R.out = pool + POOL[role] * 128;
        return R;
    };
    auto p1T = [&](int ei, int l) {
        int po = l * 5 + ei;
        P1T t;
        t.xl = pool + POOL[2 * ei] * 128;
        t.xr = pool + POOL[2 * ei + 1] * 128;
        t.csr = csrB + el.cumE[ei];
        t.cdst = cdstB + el.cumE[ei];
        t.att = att + (size_t)po * 128;
        t.sb = sbufB + el.cumE[ei];
        t.menc = mencB + (size_t)ei * RSTR;
        return t;
    };
    auto edgeT = [&](int ei, int l) {
        int po = l * 5 + ei;
        EdgeT t;
        t.xl = pool + POOL[2 * ei] * 128;
        t.csr = csrB + el.cumE[ei];
        t.off = off5 + (size_t)ei * RSTR;
        t.rank = rankB + (size_t)(2 * ei + 1) * RSTR;
        t.bias = cb + (size_t)po * 128;
        t.menc = mencB + (size_t)ei * RSTR;
        t.sb = sbufB + el.cumE[ei];
        return t;
    };

    for (int l = 0; l < 4; l++) {
        bool last = (l == 3);
        bool skipJb = (l == 2);

        // reset per-type segment maxima (independent of GEMM -> issue first)
        fill_menc_k<<<(5 * RSTR + 255) / 256, 256>>>();

        GB gb;
        int nr = 0, cum = 0;
        if (!last) {
            for (int ei = 0; ei < 5; ei++) {
                if (skipJb && ei == 1) continue;
                for (int side = 0; side < 2; side++) {
                    gb.r[nr] = makeRole(ei, side, l);
                    gb.cum[nr] = cum;
                    cum += GRIDR[2 * ei + side];
                    nr++;
                }
            }
        } else {
            for (int side = 0; side < 2; side++) {
                gb.r[nr] = makeRole(3, side, l);
                gb.cum[nr] = cum;
                cum += GRIDR[6 + side];
                nr++;
            }
        }
        gb.cum[nr] = cum;
        gb.n = nr;
        gemm_batch_k<<<cum, 256, SMEM>>>(gb);

        // pass 1: batched logits + segment max
        P1Args pa;
        int np = 0, pc = 0;
        if (!last) {
            for (int ei = 0; ei < 5; ei++) {
                if (skipJb && ei == 1) continue;
                pa.t[np] = p1T(ei, l);
                pa.cum[np] = pc;
                pc += E[ei] / 8;
                np++;
            }
        } else {
            pa.t[np] = p1T(3, l);
            pa.cum[np] = pc;
            pc += E[3] / 8;
            np++;
        }
        pa.cum[np] = pc;
        pa.n = np;
        p1_k<<<pc, 256>>>(pa);

        // pass 2: dst-parallel aggregation
        LayerED L;
        L.Wdec = Wdec; L.bdec = bdec; L.dec_out = (float*)d_out;
        if (!last) {
            L.tJ0 = edgeT(0, l); L.tJ1 = edgeT(2, l); L.tJ2 = edgeT(4, l);
            L.tB = edgeT(1, l);
            L.tF = edgeT(3, l);
            L.aggJ = agg + XOFF[1];
            L.aggB = agg + XOFF[0];
            L.aggF = agg + XOFF[2];
            L.doDecode = 0;
            int gJ = NJOINT / 8;
            int gB = skipJb ? 0 : NBASE / 8;
            int gF = NFOOT / 8;
            L.bB0 = gJ;
            L.bF0 = gJ + gB;
            edge_layer_k<<<gJ + gB + gF, 256>>>(L);
            __half* tmp = x; x = agg; agg = tmp;
        } else {
            L.tJ0 = L.tJ1 = L.tJ2 = edgeT(3, l);
            L.tB = edgeT(3, l);
            L.tF = edgeT(3, l);
            L.aggJ = L.aggB = L.aggF = agg + XOFF[2];
            L.doDecode = 1;
            L.bB0 = 0;
            L.bF0 = 0;
            edge_layer_k<<<NFOOT / 8, 256>>>(L);
        }
    }
}

// round 14
// speedup vs baseline: 1.1740x; 1.1740x over previous
#include <cuda_runtime.h>
#include <cuda_fp16.h>
#include <math.h>

#define NBASE 40000
#define NJOINT 480000
#define NFOOT 160000
#define HDIM 128
#define NEG_SLOPE 0.2f
#define RSTR 481280      // padded per-role segment stride (= 470*1024)
#define NBLK 470         // 1024-elem scan blocks per segment

// ---------------- scratch (device globals; ~1.0 GB, linker-safe) ----------------
__device__ __half g_bufA[(size_t)680000 * 128];   // x / agg ping-pong (fp16, post-relu)
__device__ __half g_bufB[(size_t)680000 * 128];
__device__ __half g_pool[(size_t)1680000 * 128];  // compact xl/xr rows (fp16)
__device__ __half g_Whi[40 * 16384];              // fp16 hi/lo split of W^T ([n][k])
__device__ __half g_Wlo[40 * 16384];
__device__ int g_rank[10 * RSTR];
__device__ int g_list[10 * RSTR];
__device__ int g_scan[10 * RSTR];
__device__ int g_deg[5 * RSTR];
__device__ int g_off5[5 * RSTR];
__device__ int g_cur5[5 * RSTR];
__device__ int g_csr[960000];
__device__ int g_cnt[16];
__device__ int g_part[10 * 512];

// ---------------- weight prep: transpose + fp16 hi/lo split ----------------
__global__ void wprep_k(const float* __restrict__ Wl, const float* __restrict__ Wr,
                        __half* __restrict__ hi, __half* __restrict__ lo) {
    int idx = blockIdx.x * 256 + threadIdx.x;
    if (idx >= 40 * 16384) return;
    int m = idx >> 14, e = idx & 16383;
    int n = e >> 7, k = e & 127;
    const float* src = (m < 20) ? (Wl + (size_t)m * 16384) : (Wr + (size_t)(m - 20) * 16384);
    float v = src[k * 128 + n];
    __half h = __float2half(v);
    __half l = __float2half(v - __half2float(h));
    hi[idx] = h; lo[idx] = l;
}

// vectorized encoder (writes post-relu fp16)
__global__ void encode_k(const float* __restrict__ x, const float* __restrict__ W,
                         const float* __restrict__ b, __half* __restrict__ y, int N, int K) {
    int idx = blockIdx.x * 256 + threadIdx.x;
    if (idx >= N * 32) return;
    int n = idx >> 5, q = idx & 31;
    float4 acc = ((const float4*)b)[q];
    for (int k = 0; k < K; k++) {
        float xv = __ldg(x + (size_t)n * K + k);
        float4 w = ((const float4*)W)[k * 32 + q];
        acc.x += xv * w.x; acc.y += xv * w.y; acc.z += xv * w.z; acc.w += xv * w.w;
    }
    __half2 h0 = __floats2half2_rn(fmaxf(acc.x, 0.f), fmaxf(acc.y, 0.f));
    __half2 h1 = __floats2half2_rn(fmaxf(acc.z, 0.f), fmaxf(acc.w, 0.f));
    uint2 p;
    p.x = *(unsigned*)&h0;
    p.y = *(unsigned*)&h1;
    *(uint2*)(y + (size_t)n * 128 + q * 4) = p;
}

// ---------------- batched prep ----------------
struct EL {
    const int* src[5];
    const int* dst[5];
    int cumE[6];
};
struct NArr { int N[10]; };

__global__ void mark_all_k(EL el, int total) {
    int gi = blockIdx.x * 256 + threadIdx.x;
    if (gi >= 2 * total) return;
    int side = gi >= total;
    int j = gi - side * total;
    int t = 0;
    while (j >= el.cumE[t + 1]) t++;
    int e = j - el.cumE[t];
    int node = side ? el.dst[t][e] : el.src[t][e];
    g_rank[(2 * t + side) * RSTR + node] = 1;
}

__global__ void bscan1_k(const int* __restrict__ v, int* __restrict__ out,
                         int* __restrict__ part) {
    __shared__ int sh[1024];
    int r = blockIdx.x / NBLK, j = blockIdx.x % NBLK;
    int i = r * RSTR + j * 1024 + threadIdx.x;
    int val = v[i];
    sh[threadIdx.x] = val;
    __syncthreads();
#pragma unroll
    for (int o = 1; o < 1024; o <<= 1) {
        int t = (threadIdx.x >= o) ? sh[threadIdx.x - o] : 0;
        __syncthreads();
        sh[threadIdx.x] += t;
        __syncthreads();
    }
    int incl = sh[threadIdx.x];
    out[i] = incl - val;
    if (threadIdx.x == 1023) part[r * 512 + j] = incl;
}
__global__ void bscan2_k(int* part) {
    __shared__ int sh[512];
    int r = blockIdx.x;
    int v = (threadIdx.x < NBLK) ? part[r * 512 + threadIdx.x] : 0;
    sh[threadIdx.x] = v;
    __syncthreads();
#pragma unroll
    for (int o = 1; o < 512; o <<= 1) {
        int t = (threadIdx.x >= o) ? sh[threadIdx.x - o] : 0;
        __syncthreads();
        sh[threadIdx.x] += t;
        __syncthreads();
    }
    if (threadIdx.x < NBLK) part[r * 512 + threadIdx.x] = sh[threadIdx.x] - v;
}
__global__ void bscan3_k(int* __restrict__ out, const int* __restrict__ part) {
    int r = blockIdx.x / NBLK, j = blockIdx.x % NBLK;
    int i = r * RSTR + j * 1024 + threadIdx.x;
    out[i] += part[r * 512 + j];
}

__global__ void bcompact_k(NArr na) {
    int i = blockIdx.x * 256 + threadIdx.x;
    if (i >= 10 * RSTR) return;
    int r = i / RSTR, li = i % RSTR;
    if (li >= na.N[r]) return;
    if (g_rank[i]) {
        int pos = g_scan[i];
        g_list[r * RSTR + pos] = li;
        g_rank[i] = pos;
    } else {
        g_rank[i] = -1;
    }
}
__global__ void getcnt_k(NArr na) {
    int r = threadIdx.x;
    if (r < 10) g_cnt[r] = g_scan[r * RSTR + na.N[r]];
}

__global__ void bhist_k(EL el, int total) {
    int j = blockIdx.x * 256 + threadIdx.x;
    if (j >= total) return;
    int t = 0;
    while (j >= el.cumE[t + 1]) t++;
    int e = j - el.cumE[t];
    atomicAdd(&g_deg[t * RSTR + el.dst[t][e]], 1);
}
__global__ void bfill_k(EL el, int total) {
    int j = blockIdx.x * 256 + threadIdx.x;
    if (j >= total) return;
    int t = 0;
    while (j >= el.cumE[t + 1]) t++;
    int e = j - el.cumE[t];
    int d = el.dst[t][e];
    int p = atomicAdd(&g_cur5[t * RSTR + d], 1);
    g_csr[el.cumE[t] + p] = g_rank[(2 * t) * RSTR + el.src[t][e]];
}

// ---------------- batched gather-GEMM (fp16 A exact, fp16 hi/lo W, 2-term MMA) ----------------
#define SAE 8704    // 64*136 fp16 elems (A)
#define SBE 17408   // 128*136 fp16 elems (B)
// smem: [A SAE][Bhi SBE][Blo SBE] = 43520 elems = 87040 B -> 2 CTAs/SM

#define LDSM4(R, addr) asm volatile( \
    "ldmatrix.sync.aligned.m8n8.x4.shared.b16 {%0,%1,%2,%3}, [%4];" \
    : "=r"((R)[0]), "=r"((R)[1]), "=r"((R)[2]), "=r"((R)[3]) : "r"(addr))

#define MMAF16(C, A, b0, b1) asm volatile( \
    "mma.sync.aligned.m16n8k16.row.col.f32.f16.f16.f32 " \
    "{%0,%1,%2,%3},{%4,%5,%6,%7},{%8,%9},{%0,%1,%2,%3};" \
    : "+f"((C)[0]), "+f"((C)[1]), "+f"((C)[2]), "+f"((C)[3]) \
    : "r"((A)[0]), "r"((A)[1]), "r"((A)[2]), "r"((A)[3]), "r"(b0), "r"(b1))

static __device__ __forceinline__ void cpasync16(unsigned dst, const void* src, int sz) {
    asm volatile("cp.async.cg.shared.global [%0], [%1], 16, %2;" :: "r"(dst), "l"(src), "r"(sz));
}

struct GR {
    const __half* A;
    const int* rowlist;
    const int* cntPtr;
    const __half* Bhi;
    const __half* Blo;
    const float* bias;
    __half* out;
};
struct GB { GR r[10]; int cum[11]; int n; };

__global__ void __launch_bounds__(256, 2) gemm_batch_k(GB gb) {
    int b = blockIdx.x;
    int k = 0;
    while (k < gb.n - 1 && b >= gb.cum[k + 1]) k++;
    GR R = gb.r[k];
    const int cnt = *R.cntPtr;
    const int row0 = (b - gb.cum[k]) * 64;
    if (row0 >= cnt) return;

    extern __shared__ __half smem[];
    const int tid = threadIdx.x;
    unsigned sA = (unsigned)__cvta_generic_to_shared(smem);
    unsigned sB = sA + SAE * 2;

    // B hi/lo via cp.async
#pragma unroll
    for (int i = 0; i < 8; i++) {
        int chunk = tid + i * 256;          // 2048 chunks of 8 fp16 (16 B)
        int row = chunk >> 4;
        int col = (chunk & 15) * 8;
        size_t off = (size_t)row * 128 + col;
        unsigned d = sB + (unsigned)(row * 136 + col) * 2;
        cpasync16(d, R.Bhi + off, 16);
        cpasync16(d + SBE * 2, R.Blo + off, 16);
    }
    // A: pure cp.async row gather (activations pre-relu'd at store time)
#pragma unroll
    for (int i = 0; i < 4; i++) {
        int chunk = tid + i * 256;          // 1024 chunks (64 rows x 16)
        int row = chunk >> 4;
        int col = (chunk & 15) * 8;
        int ok = (row0 + row) < cnt;
        int node = ok ? R.rowlist[row0 + row] : 0;
        unsigned d = sA + (unsigned)(row * 136 + col) * 2;
        cpasync16(d, R.A + (size_t)node * 128 + col, ok ? 16 : 0);
    }
    asm volatile("cp.async.commit_group;");
    asm volatile("cp.async.wait_group 0;");
    __syncthreads();

    int warp = tid >> 5, lane = tid & 31;
    int m0 = (warp >> 2) * 32;
    int n0 = (warp & 3) * 32;
    int frow = lane & 15;
    int fcolo = (lane >> 4) * 8;

    float acc[2][4][4];
#pragma unroll
    for (int a = 0; a < 2; a++)
#pragma unroll
        for (int c = 0; c < 4; c++)
#pragma unroll
            for (int r = 0; r < 4; r++) acc[a][c][r] = 0.f;

    for (int ks = 0; ks < 8; ks++) {
        int acol = ks * 16 + fcolo;
        unsigned ah[2][4];
#pragma unroll
        for (int mt = 0; mt < 2; mt++) {
            unsigned ad = sA + (unsigned)((m0 + mt * 16 + frow) * 136 + acol) * 2;
            LDSM4(ah[mt], ad);
        }
        unsigned bh[2][4], blx[2][4];
#pragma unroll
        for (int p = 0; p < 2; p++) {
            unsigned bd = sB + (unsigned)((n0 + p * 16 + frow) * 136 + acol) * 2;
            LDSM4(bh[p], bd);
            LDSM4(blx[p], bd + SBE * 2);
        }
#pragma unroll
        for (int mt = 0; mt < 2; mt++)
#pragma unroll
            for (int nt = 0; nt < 4; nt++) {
                int p = nt >> 1, o = nt & 1;
                MMAF16(acc[mt][nt], ah[mt], bh[p][o], bh[p][2 + o]);
                MMAF16(acc[mt][nt], ah[mt], blx[p][o], blx[p][2 + o]);
            }
    }

    int crow = lane >> 2, ccol = (lane & 3) * 2;
#pragma unroll
    for (int nt = 0; nt < 4; nt++) {
        int col = n0 + nt * 8 + ccol;
        float b0v = R.bias[col], b1v = R.bias[col + 1];
#pragma unroll
        for (int mt = 0; mt < 2; mt++) {
            int r = row0 + m0 + mt * 16 + crow;
            if (r < cnt)
                *(__half2*)(R.out + (size_t)r * 128 + col) =
                    __floats2half2_rn(acc[mt][nt][0] + b0v, acc[mt][nt][1] + b1v);
            if (r + 8 < cnt)
                *(__half2*)(R.out + (size_t)(r + 8) * 128 + col) =
                    __floats2half2_rn(acc[mt][nt][2] + b0v, acc[mt][nt][3] + b1v);
        }
    }
}

// ---------------- fused per-layer edge kernel (round-10 online softmax) ----------------
struct EdgeT {
    const __half* xl;
    const __half* xr;
    const int* csr;
    const int* off;
    const int* rank;
    const float* att;
    const float* bias;
};

static __device__ __forceinline__ float4 ldh4(const __half* p) {
    uint2 raw = *(const uint2*)p;
    const __half2* hp = (const __half2*)&raw;
    float2 a = __half22float2(hp[0]);
    float2 b = __half22float2(hp[1]);
    return make_float4(a.x, a.y, b.x, b.y);
}

static __device__ __forceinline__ float edge_logit(float4 xv, float4 xr4, float4 at) {
    float t0 = xv.x + xr4.x, t1 = xv.y + xr4.y, t2 = xv.z + xr4.z, t3 = xv.w + xr4.w;
    t0 = t0 > 0.f ? t0 : NEG_SLOPE * t0;
    t1 = t1 > 0.f ? t1 : NEG_SLOPE * t1;
    t2 = t2 > 0.f ? t2 : NEG_SLOPE * t2;
    t3 = t3 > 0.f ? t3 : NEG_SLOPE * t3;
    return t0 * at.x + t1 * at.y + t2 * at.z + t3 * at.w;
}

static __device__ __forceinline__ void proc_one(const EdgeT& t, int d, int lane, float4& r) {
    float4 bb = ((const float4*)t.bias)[lane];
    r.x += bb.x; r.y += bb.y; r.z += bb.z; r.w += bb.w;
    int s0 = t.off[d], s1 = t.off[d + 1];
    if (s1 <= s0) return;
    int cr = t.rank[d];
    float4 xr4 = ldh4(t.xr + (size_t)cr * 128 + lane * 4);
    float4 at = ((const float4*)t.att)[lane];
    float m = -INFINITY, den = 0.f;
    float a0 = 0.f, a1 = 0.f, a2 = 0.f, a3 = 0.f;
    int e = s0;
    for (; e + 1 < s1; e += 2) {
        int si0 = t.csr[e], si1 = t.csr[e + 1];
        float4 x0 = ldh4(t.xl + (size_t)si0 * 128 + lane * 4);
        float4 x1 = ldh4(t.xl + (size_t)si1 * 128 + lane * 4);
        float p0 = edge_logit(x0, xr4, at);
        float p1 = edge_logit(x1, xr4, at);
#pragma unroll
        for (int o = 16; o; o >>= 1) {
            p0 += __shfl_xor_sync(0xffffffffu, p0, o);
            p1 += __shfl_xor_sync(0xffffffffu, p1, o);
        }
        float mn = fmaxf(m, fmaxf(p0, p1));
        float c = __expf(m - mn);
        float w0 = __expf(p0 - mn);
        float w1 = __expf(p1 - mn);
        den = den * c + w0 + w1;
        a0 = a0 * c + w0 * x0.x + w1 * x1.x;
        a1 = a1 * c + w0 * x0.y + w1 * x1.y;
        a2 = a2 * c + w0 * x0.z + w1 * x1.z;
        a3 = a3 * c + w0 * x0.w + w1 * x1.w;
        m = mn;
    }
    if (e < s1) {
        int si = t.csr[e];
        float4 xv = ldh4(t.xl + (size_t)si * 128 + lane * 4);
        float p = edge_logit(xv, xr4, at);
#pragma unroll
        for (int o = 16; o; o >>= 1) p += __shfl_xor_sync(0xffffffffu, p, o);
        float mn = fmaxf(m, p);
        float c = __expf(m - mn);
        float w = __expf(p - mn);
        den = den * c + w;
        a0 = a0 * c + w * xv.x;
        a1 = a1 * c + w * xv.y;
        a2 = a2 * c + w * xv.z;
        a3 = a3 * c + w * xv.w;
    }
    float inv = 1.f / den;
    r.x += a0 * inv; r.y += a1 * inv; r.z += a2 * inv; r.w += a3 * inv;
}

// store with fused relu (activations consumed post-relu everywhere)
static __device__ __forceinline__ void store_agg(__half* agg, int d, int lane, float4 r) {
    __half2 p0 = __floats2half2_rn(fmaxf(r.x, 0.f), fmaxf(r.y, 0.f));
    __half2 p1 = __floats2half2_rn(fmaxf(r.z, 0.f), fmaxf(r.w, 0.f));
    uint2 packed;
    packed.x = *(unsigned*)&p0;
    packed.y = *(unsigned*)&p1;
    *(uint2*)(agg + (size_t)d * 128 + lane * 4) = packed;
}

struct LayerED {
    EdgeT tJ0, tJ1, tJ2;
    EdgeT tB;
    EdgeT tF;
    __half *aggJ, *aggB, *aggF;
    int bB0, bF0;
    const float* Wdec;
    const float* bdec;
    float* dec_out;
    int doDecode;
};

__global__ void edge_layer_k(LayerED L) {
    int blk = blockIdx.x;
    int w = threadIdx.x >> 5;
    int lane = threadIdx.x & 31;
    float4 r = make_float4(0.f, 0.f, 0.f, 0.f);
    if (blk < L.bB0) {
        int d = blk * 8 + w;
        proc_one(L.tJ0, d, lane, r);
        proc_one(L.tJ1, d, lane, r);
        proc_one(L.tJ2, d, lane, r);
        store_agg(L.aggJ, d, lane, r);
    } else if (blk < L.bF0) {
        int d = (blk - L.bB0) * 8 + w;
        proc_one(L.tB, d, lane, r);
        store_agg(L.aggB, d, lane, r);
    } else {
        int d = (blk - L.bF0) * 8 + w;
        proc_one(L.tF, d, lane, r);
        if (!L.doDecode) {
            store_agg(L.aggF, d, lane, r);
        } else {
            r.x = fmaxf(r.x, 0.f); r.y = fmaxf(r.y, 0.f);
            r.z = fmaxf(r.z, 0.f); r.w = fmaxf(r.w, 0.f);
            int h = lane * 4;
            const float* W = L.Wdec;
            float s0 = r.x * W[(h + 0) * 3 + 0] + r.y * W[(h + 1) * 3 + 0] + r.z * W[(h + 2) * 3 + 0] + r.w * W[(h + 3) * 3 + 0];
            float s1 = r.x * W[(h + 0) * 3 + 1] + r.y * W[(h + 1) * 3 + 1] + r.z * W[(h + 2) * 3 + 1] + r.w * W[(h + 3) * 3 + 1];
            float s2 = r.x * W[(h + 0) * 3 + 2] + r.y * W[(h + 1) * 3 + 2] + r.z * W[(h + 2) * 3 + 2] + r.w * W[(h + 3) * 3 + 2];
#pragma unroll
            for (int o = 16; o; o >>= 1) {
                s0 += __shfl_xor_sync(0xffffffffu, s0, o);
                s1 += __shfl_xor_sync(0xffffffffu, s1, o);
                s2 += __shfl_xor_sync(0xffffffffu, s2, o);
            }
            if (lane == 0) {
                L.dec_out[d * 3 + 0] = s0 + L.bdec[0];
                L.dec_out[d * 3 + 1] = s1 + L.bdec[1];
                L.dec_out[d * 3 + 2] = s2 + L.bdec[2];
            }
        }
    }
}

// ---------------- host orchestration ----------------
extern "C" void kernel_launch(void* const* d_in, const int* in_sizes, int n_in,
                              void* d_out, int out_size) {
    int I[27];
    if (in_sizes[1] == 768) {
        const int m[27] = {0, 3, 6, 1, 2, 4, 5, 7, 8,
                           19, 20, 21, 22, 23, 24, 25, 26,
                           9, 10, 11, 12, 13, 14, 15, 16, 17, 18};
        for (int i = 0; i < 27; i++) I[i] = m[i];
    } else {
        for (int i = 0; i < 27; i++) I[i] = i;
    }

    const float* x_in[3] = {(const float*)d_in[I[0]], (const float*)d_in[I[1]], (const float*)d_in[I[2]]};
    const float* Wenc[3] = {(const float*)d_in[I[3]], (const float*)d_in[I[5]], (const float*)d_in[I[7]]};
    const float* benc[3] = {(const float*)d_in[I[4]], (const float*)d_in[I[6]], (const float*)d_in[I[8]]};
    const float* Wl = (const float*)d_in[I[9]];
    const float* bl = (const float*)d_in[I[10]];
    const float* Wr = (const float*)d_in[I[11]];
    const float* br = (const float*)d_in[I[12]];
    const float* att = (const float*)d_in[I[13]];
    const float* cb = (const float*)d_in[I[14]];
    const float* Wdec = (const float*)d_in[I[15]];
    const float* bdec = (const float*)d_in[I[16]];
    const int *srcA[5], *dstA[5];
    int E[5];
    for (int t = 0; t < 5; t++) {
        srcA[t] = (const int*)d_in[I[17 + 2 * t]];
        dstA[t] = (const int*)d_in[I[18 + 2 * t]];
        E[t] = in_sizes[I[17 + 2 * t]];
    }

    __half *bufA, *bufB, *pool, *Whi, *Wlo;
    int *rankB, *listB, *scanB, *degB, *off5, *cur5, *csrB, *cnt, *part;
    cudaGetSymbolAddress((void**)&bufA, g_bufA);
    cudaGetSymbolAddress((void**)&bufB, g_bufB);
    cudaGetSymbolAddress((void**)&pool, g_pool);
    cudaGetSymbolAddress((void**)&Whi, g_Whi);
    cudaGetSymbolAddress((void**)&Wlo, g_Wlo);
    cudaGetSymbolAddress((void**)&rankB, g_rank);
    cudaGetSymbolAddress((void**)&listB, g_list);
    cudaGetSymbolAddress((void**)&scanB, g_scan);
    cudaGetSymbolAddress((void**)&degB, g_deg);
    cudaGetSymbolAddress((void**)&off5, g_off5);
    cudaGetSymbolAddress((void**)&cur5, g_cur5);
    cudaGetSymbolAddress((void**)&csrB, g_csr);
    cudaGetSymbolAddress((void**)&cnt, g_cnt);
    cudaGetSymbolAddress((void**)&part, g_part);

    const int Nn[3] = {NBASE, NJOINT, NFOOT};
    const int Kin[3] = {6, 2, 4};
    const size_t XOFF[3] = {0, (size_t)NBASE * 128, (size_t)(NBASE + NJOINT) * 128};
    const int sT[5] = {0, 1, 1, 1, 2};
    const int dT[5] = {1, 0, 1, 2, 1};
    const size_t POOL[10] = {0, 40000, 200000, 360000, 400000, 720000, 1040000, 1200000, 1360000, 1520000};
    const int GRIDR[10] = {625, 2500, 2500, 625, 5000, 5000, 2500, 2500, 2500, 2500};

    const int SMEM = (SAE + 2 * SBE) * 2;   // 87040 B -> 2 CTAs/SM
    cudaFuncSetAttribute(gemm_batch_k, cudaFuncAttributeMaxDynamicSharedMemorySize, SMEM);

    // ---- once-per-call prep ----
    wprep_k<<<(40 * 16384 + 255) / 256, 256>>>(Wl, Wr, Whi, Wlo);
    for (int t = 0; t < 3; t++)
        encode_k<<<(Nn[t] * 32 + 255) / 256, 256>>>(
            x_in[t], Wenc[t], benc[t], bufA + XOFF[t], Nn[t], Kin[t]);

    EL el;
    el.cumE[0] = 0;
    for (int t = 0; t < 5; t++) {
        el.src[t] = srcA[t];
        el.dst[t] = dstA[t];
        el.cumE[t + 1] = el.cumE[t] + E[t];
    }
    int Etot = el.cumE[5];
    NArr na;
    for (int ei = 0; ei < 5; ei++) {
        na.N[2 * ei] = Nn[sT[ei]];
        na.N[2 * ei + 1] = Nn[dT[ei]];
    }

    // role compaction (batched)
    cudaMemsetAsync(rankB, 0, (size_t)10 * RSTR * 4);
    mark_all_k<<<(2 * Etot + 255) / 256, 256>>>(el, Etot);
    bscan1_k<<<10 * NBLK, 1024>>>(rankB, scanB, part);
    bscan2_k<<<10, 512>>>(part);
    bscan3_k<<<10 * NBLK, 1024>>>(scanB, part);
    bcompact_k<<<(10 * RSTR + 255) / 256, 256>>>(na);
    getcnt_k<<<1, 16>>>(na);

    // CSR build (batched)
    cudaMemsetAsync(degB, 0, (size_t)5 * RSTR * 4);
    bhist_k<<<(Etot + 255) / 256, 256>>>(el, Etot);
    bscan1_k<<<5 * NBLK, 1024>>>(degB, off5, part);
    bscan2_k<<<5, 512>>>(part);
    bscan3_k<<<5 * NBLK, 1024>>>(off5, part);
    cudaMemcpyAsync(cur5, off5, (size_t)5 * RSTR * 4, cudaMemcpyDeviceToDevice);
    bfill_k<<<(Etot + 255) / 256, 256>>>(el, Etot);

    __half* x = bufA;
    __half* agg = bufB;

    auto makeRole = [&](int ei, int side, int l) {
        int role = 2 * ei + side;
        int po = l * 5 + ei;
        int wIdx = side ? (20 + po) : po;
        GR R;
        R.A = x + XOFF[side ? dT[ei] : sT[ei]];
        R.rowlist = listB + (size_t)role * RSTR;
        R.cntPtr = cnt + role;
        R.Bhi = Whi + (size_t)wIdx * 16384;
        R.Blo = Wlo + (size_t)wIdx * 16384;
        R.bias = side ? (br + (size_t)po * 128) : (bl + (size_t)po * 128);
        R.out = pool + POOL[role] * 128;
        return R;
    };
    auto edgeT = [&](int ei, int l) {
        int po = l * 5 + ei;
        EdgeT t;
        t.xl = pool + POOL[2 * ei] * 128;
        t.xr = pool + POOL[2 * ei + 1] * 128;
        t.csr = csrB + el.cumE[ei];
        t.off = off5 + (size_t)ei * RSTR;
        t.rank = rankB + (size_t)(2 * ei + 1) * RSTR;
        t.att = att + (size_t)po * 128;
        t.bias = cb + (size_t)po * 128;
        return t;
    };

    for (int l = 0; l < 4; l++) {
        bool last = (l == 3);
        bool skipJb = (l == 2);

        GB gb;
        int nr = 0, cum = 0;
        if (!last) {
            for (int ei = 0; ei < 5; ei++) {
                if (skipJb && ei == 1) continue;
                for (int side = 0; side < 2; side++) {
                    gb.r[nr] = makeRole(ei, side, l);
                    gb.cum[nr] = cum;
                    cum += GRIDR[2 * ei + side];
                    nr++;
                }
            }
        } else {
            for (int side = 0; side < 2; side++) {
                gb.r[nr] = makeRole(3, side, l);
                gb.cum[nr] = cum;
                cum += GRIDR[6 + side];
                nr++;
            }
        }
        gb.cum[nr] = cum;
        gb.n = nr;
        gemm_batch_k<<<cum, 256, SMEM>>>(gb);

        LayerED L;
        L.Wdec = Wdec; L.bdec = bdec; L.dec_out = (float*)d_out;
        if (!last) {
            L.tJ0 = edgeT(0, l); L.tJ1 = edgeT(2, l); L.tJ2 = edgeT(4, l);
            L.tB = edgeT(1, l);
            L.tF = edgeT(3, l);
            L.aggJ = agg + XOFF[1];
            L.aggB = agg + XOFF[0];
            L.aggF = agg + XOFF[2];
            L.doDecode = 0;
            int gJ = NJOINT / 8;
            int gB = skipJb ? 0 : NBASE / 8;
            int gF = NFOOT / 8;
            L.bB0 = gJ;
            L.bF0 = gJ + gB;
            edge_layer_k<<<gJ + gB + gF, 256>>>(L);
            __half* tmp = x; x = agg; agg = tmp;
        } else {
            L.tJ0 = L.tJ1 = L.tJ2 = edgeT(3, l);
            L.tB = edgeT(3, l);
            L.tF = edgeT(3, l);
            L.aggJ = L.aggB = L.aggF = agg + XOFF[2];
            L.doDecode = 1;
            L.bB0 = 0;
            L.bF0 = 0;
            edge_layer_k<<<NFOOT / 8, 256>>>(L);
        }
    }
}

// round 15
// speedup vs baseline: 1.2794x; 1.0897x over previous
#include <cuda_runtime.h>
#include <cuda_fp16.h>
#include <math.h>

#define NBASE 40000
#define NJOINT 480000
#define NFOOT 160000
#define HDIM 128
#define NEG_SLOPE 0.2f
#define RSTR 481280      // padded per-role segment stride (= 470*1024)
#define NBLK 470         // 1024-elem scan blocks per segment

// ---------------- scratch (device globals; ~1.0 GB, linker-safe) ----------------
__device__ __half g_bufA[(size_t)680000 * 128];   // x / agg ping-pong (fp16, post-relu)
__device__ __half g_bufB[(size_t)680000 * 128];
__device__ __half g_pool[(size_t)1680000 * 128];  // compact xl/xr rows (fp16)
__device__ __half g_Whi[40 * 16384];              // fp16 hi/lo split of W^T ([n][k])
__device__ __half g_Wlo[40 * 16384];
__device__ int g_rank[10 * RSTR];
__device__ int g_list[10 * RSTR];
__device__ int g_scan[10 * RSTR];
__device__ int g_deg[5 * RSTR];
__device__ int g_off5[5 * RSTR];
__device__ int g_cur5[5 * RSTR];
__device__ int g_csr[960000];
__device__ int g_cnt[16];
__device__ int g_part[10 * 512];

// ---------------- weight prep: transpose + fp16 hi/lo split ----------------
__global__ void wprep_k(const float* __restrict__ Wl, const float* __restrict__ Wr,
                        __half* __restrict__ hi, __half* __restrict__ lo) {
    int idx = blockIdx.x * 256 + threadIdx.x;
    if (idx >= 40 * 16384) return;
    int m = idx >> 14, e = idx & 16383;
    int n = e >> 7, k = e & 127;
    const float* src = (m < 20) ? (Wl + (size_t)m * 16384) : (Wr + (size_t)(m - 20) * 16384);
    float v = src[k * 128 + n];
    __half h = __float2half(v);
    __half l = __float2half(v - __half2float(h));
    hi[idx] = h; lo[idx] = l;
}

// vectorized encoder (writes post-relu fp16)
__global__ void encode_k(const float* __restrict__ x, const float* __restrict__ W,
                         const float* __restrict__ b, __half* __restrict__ y, int N, int K) {
    int idx = blockIdx.x * 256 + threadIdx.x;
    if (idx >= N * 32) return;
    int n = idx >> 5, q = idx & 31;
    float4 acc = ((const float4*)b)[q];
    for (int k = 0; k < K; k++) {
        float xv = __ldg(x + (size_t)n * K + k);
        float4 w = ((const float4*)W)[k * 32 + q];
        acc.x += xv * w.x; acc.y += xv * w.y; acc.z += xv * w.z; acc.w += xv * w.w;
    }
    __half2 h0 = __floats2half2_rn(fmaxf(acc.x, 0.f), fmaxf(acc.y, 0.f));
    __half2 h1 = __floats2half2_rn(fmaxf(acc.z, 0.f), fmaxf(acc.w, 0.f));
    uint2 p;
    p.x = *(unsigned*)&h0;
    p.y = *(unsigned*)&h1;
    *(uint2*)(y + (size_t)n * 128 + q * 4) = p;
}

// ---------------- batched prep ----------------
struct EL {
    const int* src[5];
    const int* dst[5];
    int cumE[6];
};
struct NArr { int N[10]; };

__global__ void mark_all_k(EL el, int total) {
    int gi = blockIdx.x * 256 + threadIdx.x;
    if (gi >= 2 * total) return;
    int side = gi >= total;
    int j = gi - side * total;
    int t = 0;
    while (j >= el.cumE[t + 1]) t++;
    int e = j - el.cumE[t];
    int node = side ? el.dst[t][e] : el.src[t][e];
    g_rank[(2 * t + side) * RSTR + node] = 1;
}

__global__ void bscan1_k(const int* __restrict__ v, int* __restrict__ out,
                         int* __restrict__ part) {
    __shared__ int sh[1024];
    int r = blockIdx.x / NBLK, j = blockIdx.x % NBLK;
    int i = r * RSTR + j * 1024 + threadIdx.x;
    int val = v[i];
    sh[threadIdx.x] = val;
    __syncthreads();
#pragma unroll
    for (int o = 1; o < 1024; o <<= 1) {
        int t = (threadIdx.x >= o) ? sh[threadIdx.x - o] : 0;
        __syncthreads();
        sh[threadIdx.x] += t;
        __syncthreads();
    }
    int incl = sh[threadIdx.x];
    out[i] = incl - val;
    if (threadIdx.x == 1023) part[r * 512 + j] = incl;
}
__global__ void bscan2_k(int* part) {
    __shared__ int sh[512];
    int r = blockIdx.x;
    int v = (threadIdx.x < NBLK) ? part[r * 512 + threadIdx.x] : 0;
    sh[threadIdx.x] = v;
    __syncthreads();
#pragma unroll
    for (int o = 1; o < 512; o <<= 1) {
        int t = (threadIdx.x >= o) ? sh[threadIdx.x - o] : 0;
        __syncthreads();
        sh[threadIdx.x] += t;
        __syncthreads();
    }
    if (threadIdx.x < NBLK) part[r * 512 + threadIdx.x] = sh[threadIdx.x] - v;
}
// final scan pass; optionally duplicates result into cur (for CSR fill cursors)
__global__ void bscan3_k(int* __restrict__ out, const int* __restrict__ part,
                         int* __restrict__ cur) {
    int r = blockIdx.x / NBLK, j = blockIdx.x % NBLK;
    int i = r * RSTR + j * 1024 + threadIdx.x;
    int v = out[i] + part[r * 512 + j];
    out[i] = v;
    if (cur) cur[i] = v;
}

__global__ void bcompact_k(NArr na) {
    int i = blockIdx.x * 256 + threadIdx.x;
    if (i >= 10 * RSTR) return;
    int r = i / RSTR, li = i % RSTR;
    if (li == na.N[r]) g_cnt[r] = g_scan[i];   // exclusive prefix at N = total
    if (li >= na.N[r]) return;
    if (g_rank[i]) {
        int pos = g_scan[i];
        g_list[r * RSTR + pos] = li;
        g_rank[i] = pos;
    } else {
        g_rank[i] = -1;
    }
}

__global__ void bhist_k(EL el, int total) {
    int j = blockIdx.x * 256 + threadIdx.x;
    if (j >= total) return;
    int t = 0;
    while (j >= el.cumE[t + 1]) t++;
    int e = j - el.cumE[t];
    atomicAdd(&g_deg[t * RSTR + el.dst[t][e]], 1);
}
__global__ void bfill_k(EL el, int total) {
    int j = blockIdx.x * 256 + threadIdx.x;
    if (j >= total) return;
    int t = 0;
    while (j >= el.cumE[t + 1]) t++;
    int e = j - el.cumE[t];
    int d = el.dst[t][e];
    int p = atomicAdd(&g_cur5[t * RSTR + d], 1);
    g_csr[el.cumE[t] + p] = g_rank[(2 * t) * RSTR + el.src[t][e]];
}

// ---------------- batched gather-GEMM (fp16 A exact, fp16 hi/lo W, 2-term MMA) ----------------
#define SAE 8704    // 64*136 fp16 elems (A)
#define SBE 17408   // 128*136 fp16 elems (B)
// smem: [A SAE][Bhi SBE][Blo SBE] = 43520 elems = 87040 B -> 2 CTAs/SM

#define LDSM4(R, addr) asm volatile( \
    "ldmatrix.sync.aligned.m8n8.x4.shared.b16 {%0,%1,%2,%3}, [%4];" \
    : "=r"((R)[0]), "=r"((R)[1]), "=r"((R)[2]), "=r"((R)[3]) : "r"(addr))

#define MMAF16(C, A, b0, b1) asm volatile( \
    "mma.sync.aligned.m16n8k16.row.col.f32.f16.f16.f32 " \
    "{%0,%1,%2,%3},{%4,%5,%6,%7},{%8,%9},{%0,%1,%2,%3};" \
    : "+f"((C)[0]), "+f"((C)[1]), "+f"((C)[2]), "+f"((C)[3]) \
    : "r"((A)[0]), "r"((A)[1]), "r"((A)[2]), "r"((A)[3]), "r"(b0), "r"(b1))

static __device__ __forceinline__ void cpasync16(unsigned dst, const void* src, int sz) {
    asm volatile("cp.async.cg.shared.global [%0], [%1], 16, %2;" :: "r"(dst), "l"(src), "r"(sz));
}

struct GR {
    const __half* A;
    const int* rowlist;
    const int* cntPtr;
    const __half* Bhi;
    const __half* Blo;
    const float* bias;
    __half* out;
};
struct GB { GR r[10]; int cum[11]; int n; };

__global__ void __launch_bounds__(256, 2) gemm_batch_k(GB gb) {
    int b = blockIdx.x;
    int k = 0;
    while (k < gb.n - 1 && b >= gb.cum[k + 1]) k++;
    GR R = gb.r[k];
    const int cnt = *R.cntPtr;
    const int row0 = (b - gb.cum[k]) * 64;
    if (row0 >= cnt) return;

    extern __shared__ __half smem[];
    const int tid = threadIdx.x;
    unsigned sA = (unsigned)__cvta_generic_to_shared(smem);
    unsigned sB = sA + SAE * 2;

    // B hi/lo via cp.async
#pragma unroll
    for (int i = 0; i < 8; i++) {
        int chunk = tid + i * 256;          // 2048 chunks of 8 fp16 (16 B)
        int row = chunk >> 4;
        int col = (chunk & 15) * 8;
        size_t off = (size_t)row * 128 + col;
        unsigned d = sB + (unsigned)(row * 136 + col) * 2;
        cpasync16(d, R.Bhi + off, 16);
        cpasync16(d + SBE * 2, R.Blo + off, 16);
    }
    // A: pure cp.async row gather (activations pre-relu'd at store time)
#pragma unroll
    for (int i = 0; i < 4; i++) {
        int chunk = tid + i * 256;          // 1024 chunks (64 rows x 16)
        int row = chunk >> 4;
        int col = (chunk & 15) * 8;
        int ok = (row0 + row) < cnt;
        int node = ok ? R.rowlist[row0 + row] : 0;
        unsigned d = sA + (unsigned)(row * 136 + col) * 2;
        cpasync16(d, R.A + (size_t)node * 128 + col, ok ? 16 : 0);
    }
    asm volatile("cp.async.commit_group;");
    asm volatile("cp.async.wait_group 0;");
    __syncthreads();

    int warp = tid >> 5, lane = tid & 31;
    int m0 = (warp >> 2) * 32;
    int n0 = (warp & 3) * 32;
    int frow = lane & 15;
    int fcolo = (lane >> 4) * 8;

    float acc[2][4][4];
#pragma unroll
    for (int a = 0; a < 2; a++)
#pragma unroll
        for (int c = 0; c < 4; c++)
#pragma unroll
            for (int r = 0; r < 4; r++) acc[a][c][r] = 0.f;

    for (int ks = 0; ks < 8; ks++) {
        int acol = ks * 16 + fcolo;
        unsigned ah[2][4];
#pragma unroll
        for (int mt = 0; mt < 2; mt++) {
            unsigned ad = sA + (unsigned)((m0 + mt * 16 + frow) * 136 + acol) * 2;
            LDSM4(ah[mt], ad);
        }
        unsigned bh[2][4], blx[2][4];
#pragma unroll
        for (int p = 0; p < 2; p++) {
            unsigned bd = sB + (unsigned)((n0 + p * 16 + frow) * 136 + acol) * 2;
            LDSM4(bh[p], bd);
            LDSM4(blx[p], bd + SBE * 2);
        }
#pragma unroll
        for (int mt = 0; mt < 2; mt++)
#pragma unroll
            for (int nt = 0; nt < 4; nt++) {
                int p = nt >> 1, o = nt & 1;
                MMAF16(acc[mt][nt], ah[mt], bh[p][o], bh[p][2 + o]);
                MMAF16(acc[mt][nt], ah[mt], blx[p][o], blx[p][2 + o]);
            }
    }

    int crow = lane >> 2, ccol = (lane & 3) * 2;
#pragma unroll
    for (int nt = 0; nt < 4; nt++) {
        int col = n0 + nt * 8 + ccol;
        float b0v = R.bias[col], b1v = R.bias[col + 1];
#pragma unroll
        for (int mt = 0; mt < 2; mt++) {
            int r = row0 + m0 + mt * 16 + crow;
            if (r < cnt)
                *(__half2*)(R.out + (size_t)r * 128 + col) =
                    __floats2half2_rn(acc[mt][nt][0] + b0v, acc[mt][nt][1] + b1v);
            if (r + 8 < cnt)
                *(__half2*)(R.out + (size_t)(r + 8) * 128 + col) =
                    __floats2half2_rn(acc[mt][nt][2] + b0v, acc[mt][nt][3] + b1v);
        }
    }
}

// ---------------- fused per-layer edge kernel with deg-1 fast path ----------------
struct EdgeT {
    const __half* xl;
    const __half* xr;
    const int* csr;
    const int* off;
    const int* rank;
    const float* att;
    const float* bias;
};

static __device__ __forceinline__ float4 ldh4(const __half* p) {
    uint2 raw = *(const uint2*)p;
    const __half2* hp = (const __half2*)&raw;
    float2 a = __half22float2(hp[0]);
    float2 b = __half22float2(hp[1]);
    return make_float4(a.x, a.y, b.x, b.y);
}

static __device__ __forceinline__ float edge_logit(float4 xv, float4 xr4, float4 at) {
    float t0 = xv.x + xr4.x, t1 = xv.y + xr4.y, t2 = xv.z + xr4.z, t3 = xv.w + xr4.w;
    t0 = t0 > 0.f ? t0 : NEG_SLOPE * t0;
    t1 = t1 > 0.f ? t1 : NEG_SLOPE * t1;
    t2 = t2 > 0.f ? t2 : NEG_SLOPE * t2;
    t3 = t3 > 0.f ? t3 : NEG_SLOPE * t3;
    return t0 * at.x + t1 * at.y + t2 * at.z + t3 * at.w;
}

// deg>=2 online softmax, first edge preloaded in x1 (m seeded at its logit)
static __device__ __forceinline__ void soft_multi(const EdgeT& t, int d, int s0, int s1,
                                                  int lane, float4 x1, float4& r) {
    int cr = t.rank[d];
    float4 xr4 = ldh4(t.xr + (size_t)cr * 128 + lane * 4);
    float4 at = ((const float4*)t.att)[lane];
    float p0 = edge_logit(x1, xr4, at);
#pragma unroll
    for (int o = 16; o; o >>= 1) p0 += __shfl_xor_sync(0xffffffffu, p0, o);
    float m = p0, den = 1.f;
    float a0 = x1.x, a1 = x1.y, a2 = x1.z, a3 = x1.w;
    int e = s0 + 1;
    for (; e + 1 < s1; e += 2) {
        int si0 = t.csr[e], si1 = t.csr[e + 1];
        float4 y0 = ldh4(t.xl + (size_t)si0 * 128 + lane * 4);
        float4 y1 = ldh4(t.xl + (size_t)si1 * 128 + lane * 4);
        float q0 = edge_logit(y0, xr4, at);
        float q1 = edge_logit(y1, xr4, at);
#pragma unroll
        for (int o = 16; o; o >>= 1) {
            q0 += __shfl_xor_sync(0xffffffffu, q0, o);
            q1 += __shfl_xor_sync(0xffffffffu, q1, o);
        }
        float mn = fmaxf(m, fmaxf(q0, q1));
        float c = __expf(m - mn);
        float w0 = __expf(q0 - mn);
        float w1 = __expf(q1 - mn);
        den = den * c + w0 + w1;
        a0 = a0 * c + w0 * y0.x + w1 * y1.x;
        a1 = a1 * c + w0 * y0.y + w1 * y1.y;
        a2 = a2 * c + w0 * y0.z + w1 * y1.z;
        a3 = a3 * c + w0 * y0.w + w1 * y1.w;
        m = mn;
    }
    if (e < s1) {
        int si = t.csr[e];
        float4 yv = ldh4(t.xl + (size_t)si * 128 + lane * 4);
        float q = edge_logit(yv, xr4, at);
#pragma unroll
        for (int o = 16; o; o >>= 1) q += __shfl_xor_sync(0xffffffffu, q, o);
        float mn = fmaxf(m, q);
        float c = __expf(m - mn);
        float w = __expf(q - mn);
        den = den * c + w;
        a0 = a0 * c + w * yv.x;
        a1 = a1 * c + w * yv.y;
        a2 = a2 * c + w * yv.z;
        a3 = a3 * c + w * yv.w;
    }
    float inv = 1.f / den;
    r.x += a0 * inv; r.y += a1 * inv; r.z += a2 * inv; r.w += a3 * inv;
}

// single edge-type with deg-1 fast path
static __device__ __forceinline__ void proc_fast(const EdgeT& t, int d, int lane, float4& r) {
    float4 bb = ((const float4*)t.bias)[lane];
    r.x += bb.x; r.y += bb.y; r.z += bb.z; r.w += bb.w;
    int s0 = t.off[d], s1 = t.off[d + 1];
    if (s1 <= s0) return;
    int fi = t.csr[s0];
    float4 x1 = ldh4(t.xl + (size_t)fi * 128 + lane * 4);
    if (s1 - s0 == 1) {
        r.x += x1.x; r.y += x1.y; r.z += x1.z; r.w += x1.w;   // softmax of 1 elem == 1
        return;
    }
    soft_multi(t, d, s0, s1, lane, x1, r);
}

// joint dst: three edge types with cross-type prefetch of off/csr/first-xl
static __device__ __forceinline__ void edge_joint3(const EdgeT& tA, const EdgeT& tB,
                                                   const EdgeT& tC, int d, int lane,
                                                   float4& r) {
    int s0a = tA.off[d], s1a = tA.off[d + 1];
    int s0b = tB.off[d], s1b = tB.off[d + 1];
    int s0c = tC.off[d], s1c = tC.off[d + 1];
    {
        float4 b0 = ((const float4*)tA.bias)[lane];
        float4 b1 = ((const float4*)tB.bias)[lane];
        float4 b2 = ((const float4*)tC.bias)[lane];
        r.x += b0.x + b1.x + b2.x;
        r.y += b0.y + b1.y + b2.y;
        r.z += b0.z + b1.z + b2.z;
        r.w += b0.w + b1.w + b2.w;
    }
    int dA = s1a - s0a, dB = s1b - s0b, dC = s1c - s0c;
    int fiA = 0, fiB = 0, fiC = 0;
    if (dA > 0) fiA = tA.csr[s0a];
    if (dB > 0) fiB = tB.csr[s0b];
    if (dC > 0) fiC = tC.csr[s0c];
    float4 xA = make_float4(0.f, 0.f, 0.f, 0.f);
    float4 xB = make_float4(0.f, 0.f, 0.f, 0.f);
    float4 xC = make_float4(0.f, 0.f, 0.f, 0.f);
    if (dA > 0) xA = ldh4(tA.xl + (size_t)fiA * 128 + lane * 4);
    if (dB > 0) xB = ldh4(tB.xl + (size_t)fiB * 128 + lane * 4);
    if (dC > 0) xC = ldh4(tC.xl + (size_t)fiC * 128 + lane * 4);
    if (dA == 1) { r.x += xA.x; r.y += xA.y; r.z += xA.z; r.w += xA.w; }
    else if (dA > 1) soft_multi(tA, d, s0a, s1a, lane, xA, r);
    if (dB == 1) { r.x += xB.x; r.y += xB.y; r.z += xB.z; r.w += xB.w; }
    else if (dB > 1) soft_multi(tB, d, s0b, s1b, lane, xB, r);
    if (dC == 1) { r.x += xC.x; r.y += xC.y; r.z += xC.z; r.w += xC.w; }
    else if (dC > 1) soft_multi(tC, d, s0c, s1c, lane, xC, r);
}

// store with fused relu (activations consumed post-relu everywhere)
static __device__ __forceinline__ void store_agg(__half* agg, int d, int lane, float4 r) {
    __half2 p0 = __floats2half2_rn(fmaxf(r.x, 0.f), fmaxf(r.y, 0.f));
    __half2 p1 = __floats2half2_rn(fmaxf(r.z, 0.f), fmaxf(r.w, 0.f));
    uint2 packed;
    packed.x = *(unsigned*)&p0;
    packed.y = *(unsigned*)&p1;
    *(uint2*)(agg + (size_t)d * 128 + lane * 4) = packed;
}

struct LayerED {
    EdgeT tJ0, tJ1, tJ2;
    EdgeT tB;
    EdgeT tF;
    __half *aggJ, *aggB, *aggF;
    int bB0, bF0;
    const float* Wdec;
    const float* bdec;
    float* dec_out;
    int doDecode;
};

__global__ void edge_layer_k(LayerED L) {
    int blk = blockIdx.x;
    int w = threadIdx.x >> 5;
    int lane = threadIdx.x & 31;
    float4 r = make_float4(0.f, 0.f, 0.f, 0.f);
    if (blk < L.bB0) {
        int d = blk * 8 + w;
        edge_joint3(L.tJ0, L.tJ1, L.tJ2, d, lane, r);
        store_agg(L.aggJ, d, lane, r);
    } else if (blk < L.bF0) {
        int d = (blk - L.bB0) * 8 + w;
        proc_fast(L.tB, d, lane, r);
        store_agg(L.aggB, d, lane, r);
    } else {
        int d = (blk - L.bF0) * 8 + w;
        proc_fast(L.tF, d, lane, r);
        if (!L.doDecode) {
            store_agg(L.aggF, d, lane, r);
        } else {
            r.x = fmaxf(r.x, 0.f); r.y = fmaxf(r.y, 0.f);
            r.z = fmaxf(r.z, 0.f); r.w = fmaxf(r.w, 0.f);
            int h = lane * 4;
            const float* W = L.Wdec;
            float s0 = r.x * W[(h + 0) * 3 + 0] + r.y * W[(h + 1) * 3 + 0] + r.z * W[(h + 2) * 3 + 0] + r.w * W[(h + 3) * 3 + 0];
            float s1 = r.x * W[(h + 0) * 3 + 1] + r.y * W[(h + 1) * 3 + 1] + r.z * W[(h + 2) * 3 + 1] + r.w * W[(h + 3) * 3 + 1];
            float s2 = r.x * W[(h + 0) * 3 + 2] + r.y * W[(h + 1) * 3 + 2] + r.z * W[(h + 2) * 3 + 2] + r.w * W[(h + 3) * 3 + 2];
#pragma unroll
            for (int o = 16; o; o >>= 1) {
                s0 += __shfl_xor_sync(0xffffffffu, s0, o);
                s1 += __shfl_xor_sync(0xffffffffu, s1, o);
                s2 += __shfl_xor_sync(0xffffffffu, s2, o);
            }
            if (lane == 0) {
                L.dec_out[d * 3 + 0] = s0 + L.bdec[0];
                L.dec_out[d * 3 + 1] = s1 + L.bdec[1];
                L.dec_out[d * 3 + 2] = s2 + L.bdec[2];
            }
        }
    }
}

// ---------------- host orchestration ----------------
extern "C" void kernel_launch(void* const* d_in, const int* in_sizes, int n_in,
                              void* d_out, int out_size) {
    int I[27];
    if (in_sizes[1] == 768) {
        const int m[27] = {0, 3, 6, 1, 2, 4, 5, 7, 8,
                           19, 20, 21, 22, 23, 24, 25, 26,
                           9, 10, 11, 12, 13, 14, 15, 16, 17, 18};
        for (int i = 0; i < 27; i++) I[i] = m[i];
    } else {
        for (int i = 0; i < 27; i++) I[i] = i;
    }

    const float* x_in[3] = {(const float*)d_in[I[0]], (const float*)d_in[I[1]], (const float*)d_in[I[2]]};
    const float* Wenc[3] = {(const float*)d_in[I[3]], (const float*)d_in[I[5]], (const float*)d_in[I[7]]};
    const float* benc[3] = {(const float*)d_in[I[4]], (const float*)d_in[I[6]], (const float*)d_in[I[8]]};
    const float* Wl = (const float*)d_in[I[9]];
    const float* bl = (const float*)d_in[I[10]];
    const float* Wr = (const float*)d_in[I[11]];
    const float* br = (const float*)d_in[I[12]];
    const float* att = (const float*)d_in[I[13]];
    const float* cb = (const float*)d_in[I[14]];
    const float* Wdec = (const float*)d_in[I[15]];
    const float* bdec = (const float*)d_in[I[16]];
    const int *srcA[5], *dstA[5];
    int E[5];
    for (int t = 0; t < 5; t++) {
        srcA[t] = (const int*)d_in[I[17 + 2 * t]];
        dstA[t] = (const int*)d_in[I[18 + 2 * t]];
        E[t] = in_sizes[I[17 + 2 * t]];
    }

    __half *bufA, *bufB, *pool, *Whi, *Wlo;
    int *rankB, *listB, *scanB, *degB, *off5, *cur5, *csrB, *cnt, *part;
    cudaGetSymbolAddress((void**)&bufA, g_bufA);
    cudaGetSymbolAddress((void**)&bufB, g_bufB);
    cudaGetSymbolAddress((void**)&pool, g_pool);
    cudaGetSymbolAddress((void**)&Whi, g_Whi);
    cudaGetSymbolAddress((void**)&Wlo, g_Wlo);
    cudaGetSymbolAddress((void**)&rankB, g_rank);
    cudaGetSymbolAddress((void**)&listB, g_list);
    cudaGetSymbolAddress((void**)&scanB, g_scan);
    cudaGetSymbolAddress((void**)&degB, g_deg);
    cudaGetSymbolAddress((void**)&off5, g_off5);
    cudaGetSymbolAddress((void**)&cur5, g_cur5);
    cudaGetSymbolAddress((void**)&csrB, g_csr);
    cudaGetSymbolAddress((void**)&cnt, g_cnt);
    cudaGetSymbolAddress((void**)&part, g_part);

    const int Nn[3] = {NBASE, NJOINT, NFOOT};
    const int Kin[3] = {6, 2, 4};
    const size_t XOFF[3] = {0, (size_t)NBASE * 128, (size_t)(NBASE + NJOINT) * 128};
    const int sT[5] = {0, 1, 1, 1, 2};
    const int dT[5] = {1, 0, 1, 2, 1};
    const size_t POOL[10] = {0, 40000, 200000, 360000, 400000, 720000, 1040000, 1200000, 1360000, 1520000};
    const int GRIDR[10] = {625, 2500, 2500, 625, 5000, 5000, 2500, 2500, 2500, 2500};

    const int SMEM = (SAE + 2 * SBE) * 2;   // 87040 B -> 2 CTAs/SM
    cudaFuncSetAttribute(gemm_batch_k, cudaFuncAttributeMaxDynamicSharedMemorySize, SMEM);

    // ---- once-per-call prep ----
    wprep_k<<<(40 * 16384 + 255) / 256, 256>>>(Wl, Wr, Whi, Wlo);
    for (int t = 0; t < 3; t++)
        encode_k<<<(Nn[t] * 32 + 255) / 256, 256>>>(
            x_in[t], Wenc[t], benc[t], bufA + XOFF[t], Nn[t], Kin[t]);

    EL el;
    el.cumE[0] = 0;
    for (int t = 0; t < 5; t++) {
        el.src[t] = srcA[t];
        el.dst[t] = dstA[t];
        el.cumE[t + 1] = el.cumE[t] + E[t];
    }
    int Etot = el.cumE[5];
    NArr na;
    for (int ei = 0; ei < 5; ei++) {
        na.N[2 * ei] = Nn[sT[ei]];
        na.N[2 * ei + 1] = Nn[dT[ei]];
    }

    // role compaction (batched)
    cudaMemsetAsync(rankB, 0, (size_t)10 * RSTR * 4);
    mark_all_k<<<(2 * Etot + 255) / 256, 256>>>(el, Etot);
    bscan1_k<<<10 * NBLK, 1024>>>(rankB, scanB, part);
    bscan2_k<<<10, 512>>>(part);
    bscan3_k<<<10 * NBLK, 1024>>>(scanB, part, nullptr);
    bcompact_k<<<(10 * RSTR + 255) / 256, 256>>>(na);

    // CSR build (batched); bscan3 dual-writes the fill cursors
    cudaMemsetAsync(degB, 0, (size_t)5 * RSTR * 4);
    bhist_k<<<(Etot + 255) / 256, 256>>>(el, Etot);
    bscan1_k<<<5 * NBLK, 1024>>>(degB, off5, part);
    bscan2_k<<<5, 512>>>(part);
    bscan3_k<<<5 * NBLK, 1024>>>(off5, part, cur5);
    bfill_k<<<(Etot + 255) / 256, 256>>>(el, Etot);

    __half* x = bufA;
    __half* agg = bufB;

    auto makeRole = [&](int ei, int side, int l) {
        int role = 2 * ei + side;
        int po = l * 5 + ei;
        int wIdx = side ? (20 + po) : po;
        GR R;
        R.A = x + XOFF[side ? dT[ei] : sT[ei]];
        R.rowlist = listB + (size_t)role * RSTR;
        R.cntPtr = cnt + role;
        R.Bhi = Whi + (size_t)wIdx * 16384;
        R.Blo = Wlo + (size_t)wIdx * 16384;
        R.bias = side ? (br + (size_t)po * 128) : (bl + (size_t)po * 128);
        R.out = pool + POOL[role] * 128;
        return R;
    };
    auto edgeT = [&](int ei, int l) {
        int po = l * 5 + ei;
        EdgeT t;
        t.xl = pool + POOL[2 * ei] * 128;
        t.xr = pool + POOL[2 * ei + 1] * 128;
        t.csr = csrB + el.cumE[ei];
        t.off = off5 + (size_t)ei * RSTR;
        t.rank = rankB + (size_t)(2 * ei + 1) * RSTR;
        t.att = att + (size_t)po * 128;
        t.bias = cb + (size_t)po * 128;
        return t;
    };

    for (int l = 0; l < 4; l++) {
        bool last = (l == 3);
        bool skipJb = (l == 2);

        GB gb;
        int nr = 0, cum = 0;
        if (!last) {
            for (int ei = 0; ei < 5; ei++) {
                if (skipJb && ei == 1) continue;
                for (int side = 0; side < 2; side++) {
                    gb.r[nr] = makeRole(ei, side, l);
                    gb.cum[nr] = cum;
                    cum += GRIDR[2 * ei + side];
                    nr++;
                }
            }
        } else {
            for (int side = 0; side < 2; side++) {
                gb.r[nr] = makeRole(3, side, l);
                gb.cum[nr] = cum;
                cum += GRIDR[6 + side];
                nr++;
            }
        }
        gb.cum[nr] = cum;
        gb.n = nr;
        gemm_batch_k<<<cum, 256, SMEM>>>(gb);

        LayerED L;
        L.Wdec = Wdec; L.bdec = bdec; L.dec_out = (float*)d_out;
        if (!last) {
            L.tJ0 = edgeT(0, l); L.tJ1 = edgeT(2, l); L.tJ2 = edgeT(4, l);
            L.tB = edgeT(1, l);
            L.tF = edgeT(3, l);
            L.aggJ = agg + XOFF[1];
            L.aggB = agg + XOFF[0];
            L.aggF = agg + XOFF[2];
            L.doDecode = 0;
            int gJ = NJOINT / 8;
            int gB = skipJb ? 0 : NBASE / 8;
            int gF = NFOOT / 8;
            L.bB0 = gJ;
            L.bF0 = gJ + gB;
            edge_layer_k<<<gJ + gB + gF, 256>>>(L);
            __half* tmp = x; x = agg; agg = tmp;
        } else {
            L.tJ0 = L.tJ1 = L.tJ2 = edgeT(3, l);
            L.tB = edgeT(3, l);
            L.tF = edgeT(3, l);
            L.aggJ = L.aggB = L.aggF = agg + XOFF[2];
            L.doDecode = 1;
            L.bB0 = 0;
            L.bF0 = 0;
            edge_layer_k<<<NFOOT / 8, 256>>>(L);
        }
    }
}